// round 16
// baseline (speedup 1.0000x reference)
#include <cuda_runtime.h>
#include <cuda_bf16.h>
#include <cstdint>
#include <cstddef>

// Problem dims
#define TT 512
#define BB 64
#define HH 1024
#define NG 4096              // 4*H, gate-interleaved: m (= n') = 4*j + gate(f,i,g,o)
#define KK 1024
#define KK2 2048             // stored K: [hi | lo]
#define BH (BB*HH)
#define BG (BB*NG)

typedef __nv_bfloat16 bf16;

// -------- device scratch (no allocations allowed) --------
__device__ __align__(16) bf16 g_Wx2[(size_t)NG * KK2]; // [m][hi|lo] for xproj
__device__ __align__(16) bf16 g_Wh2[(size_t)NG * KK2]; // [m][hi|lo] for recurrence
__device__ __align__(16) bf16 g_X2[(size_t)TT * BB * KK2]; // [s][hi|lo]
__device__ __align__(16) bf16 g_h2[2][BB * KK2];       // double-buffered h splits [b][hi|lo]
__device__ float g_ball[NG];
__device__ float g_XW[(size_t)TT * BB * NG];
__device__ unsigned int g_bar[TT];                     // root barrier counters
__device__ unsigned int g_barg[TT * 512];              // 16 group counters x 32-int pad per t

// ---------------- low-level helpers (sm_80+ only) ----------------
__device__ __forceinline__ uint32_t smem_u32(const void* p) {
    uint32_t a;
    asm("{ .reg .u64 t; cvta.to.shared.u64 t, %1; cvt.u32.u64 %0, t; }" : "=r"(a) : "l"(p));
    return a;
}
__device__ __forceinline__ void cp16(uint32_t dst, const void* src) {
    asm volatile("cp.async.cg.shared.global [%0], [%1], 16;" :: "r"(dst), "l"(src) : "memory");
}
#define CP_COMMIT() asm volatile("cp.async.commit_group;" ::: "memory")
#define CP_WAIT1()  asm volatile("cp.async.wait_group 1;" ::: "memory")
#define CP_WAIT0()  asm volatile("cp.async.wait_group 0;" ::: "memory")

__device__ __forceinline__ float lds_f32(uint32_t a) {
    float v; asm volatile("ld.shared.f32 %0, [%1];" : "=f"(v) : "r"(a)); return v;
}
__device__ __forceinline__ void sts128(uint32_t a, uint4 v) {
    asm volatile("st.shared.v4.b32 [%0], {%1,%2,%3,%4};" :: "r"(a), "r"(v.x), "r"(v.y), "r"(v.z), "r"(v.w) : "memory");
}
__device__ __forceinline__ void sts_f32(uint32_t a, float v) {
    asm volatile("st.shared.f32 [%0], %1;" :: "r"(a), "f"(v) : "memory");
}
__device__ __forceinline__ void ldm4(uint32_t* r, uint32_t a) {
    asm volatile("ldmatrix.sync.aligned.m8n8.x4.shared.b16 {%0,%1,%2,%3}, [%4];"
        : "=r"(r[0]), "=r"(r[1]), "=r"(r[2]), "=r"(r[3]) : "r"(a));
}
__device__ __forceinline__ void mma16816(float* c,
                                         uint32_t a0, uint32_t a1, uint32_t a2, uint32_t a3,
                                         uint32_t b0, uint32_t b1) {
    asm volatile(
        "mma.sync.aligned.m16n8k16.row.col.f32.bf16.bf16.f32 "
        "{%0,%1,%2,%3}, {%4,%5,%6,%7}, {%8,%9}, {%0,%1,%2,%3};"
        : "+f"(c[0]), "+f"(c[1]), "+f"(c[2]), "+f"(c[3])
        : "r"(a0), "r"(a1), "r"(a2), "r"(a3), "r"(b0), "r"(b1));
}

// ---------------- prep kernels ----------------
// K-MAJOR index convention (idx = k*NG + n) — bias guard `idx < NG` valid only here.
__global__ void repack_kernel(const float* __restrict__ Wf, const float* __restrict__ Wi,
                              const float* __restrict__ Wg, const float* __restrict__ Wo,
                              const float* __restrict__ bf_, const float* __restrict__ bi_,
                              const float* __restrict__ bg_, const float* __restrict__ bo_) {
    int idx = blockIdx.x * 256 + threadIdx.x;   // idx = k*NG + n
    int k = idx >> 12;
    int n = idx & (NG - 1);
    int c = n >> 2, g = n & 3;
    const float* W = (g == 0) ? Wf : (g == 1) ? Wi : (g == 2) ? Wg : Wo;
    float wx = W[(size_t)k * HH + c];
    float wh = W[(size_t)(k + 1024) * HH + c];
    bf16 xh = __float2bfloat16(wx);
    g_Wx2[(size_t)n * KK2 + k]        = xh;
    g_Wx2[(size_t)n * KK2 + 1024 + k] = __float2bfloat16(wx - __bfloat162float(xh));
    bf16 hh = __float2bfloat16(wh);
    g_Wh2[(size_t)n * KK2 + k]        = hh;
    g_Wh2[(size_t)n * KK2 + 1024 + k] = __float2bfloat16(wh - __bfloat162float(hh));
    if (idx < NG) {
        const float* bv = (g == 0) ? bf_ : (g == 1) ? bi_ : (g == 2) ? bg_ : bo_;
        g_ball[idx] = bv[c];
    }
    if (idx < TT) g_bar[idx] = 0u;
    if (idx < TT * 512) g_barg[idx] = 0u;
}

__global__ void convx_kernel(const float* __restrict__ inp) {
    int idx = blockIdx.x * 256 + threadIdx.x;   // s*1024 + k
    int s = idx >> 10, k = idx & 1023;
    float v = inp[idx];
    bf16 h = __float2bfloat16(v);
    g_X2[(size_t)s * KK2 + k]        = h;
    g_X2[(size_t)s * KK2 + 1024 + k] = __float2bfloat16(v - __bfloat162float(h));
}

// ================= xproj (round-15 verbatim, at tensor roofline) =================
#define X_P   136                      // smem pitch (bf16)
#define X_TB  (128 * X_P * 2)          // 34816 B per tile buffer
#define X_SMEM (4 * X_TB)              // A0,A1,B0,B1 = 139264

__device__ __forceinline__ void xp_issue(uint32_t sb, int tid, int ck, int m0, int n0) {
    uint32_t ab = sb + (uint32_t)(ck & 1) * X_TB;
    uint32_t bb = sb + 2 * X_TB + (uint32_t)(ck & 1) * X_TB;
    int ka = (ck < 16) ? ck * 128 : (ck - 16) * 128;   // A: hi, lo, hi
    int kb = (ck < 8) ? ck * 128 : (ck - 8) * 128;     // B: hi, hi, lo
#pragma unroll
    for (int it = 0; it < 8; ++it) {
        int j = tid + it * 256;
        int r = j >> 4, kq = j & 15;
        uint32_t off = (uint32_t)(r * X_P + kq * 8) * 2;
        cp16(ab + off, g_Wx2 + (size_t)(m0 + r) * KK2 + ka + kq * 8);
        cp16(bb + off, g_X2 + (size_t)(n0 + r) * KK2 + kb + kq * 8);
    }
    CP_COMMIT();
}

__global__ __launch_bounds__(256) void xproj_kernel() {
    extern __shared__ __align__(16) char smem[];
    uint32_t sb = smem_u32(smem);
    const int tid = threadIdx.x;
    const int w = tid >> 5, lane = tid & 31;
    const int g = lane >> 2, c4 = lane & 3;
    const int m0 = blockIdx.x * 128, n0 = blockIdx.y * 128;
    const int mg = w >> 1, ngp = w & 1;     // warp tile: m32 x n64
    const int lrow = lane & 15;
    const int lko  = (lane >> 4) * 8;

    float acc[2][8][4];
#pragma unroll
    for (int a = 0; a < 2; ++a)
#pragma unroll
        for (int b = 0; b < 8; ++b)
#pragma unroll
            for (int d = 0; d < 4; ++d) acc[a][b][d] = 0.f;

    xp_issue(sb, tid, 0, m0, n0);
    for (int ck = 0; ck < 24; ++ck) {
        if (ck < 23) { xp_issue(sb, tid, ck + 1, m0, n0); CP_WAIT1(); }
        else CP_WAIT0();
        __syncthreads();
        uint32_t ab = sb + (uint32_t)(ck & 1) * X_TB;
        uint32_t bb = sb + 2 * X_TB + (uint32_t)(ck & 1) * X_TB;
#pragma unroll
        for (int kk = 0; kk < 8; ++kk) {
            int kb = kk * 16 + lko;
            uint32_t af[2][4], bf_[4][4];
#pragma unroll
            for (int mt = 0; mt < 2; ++mt)
                ldm4(af[mt], ab + (uint32_t)((32 * mg + 16 * mt + lrow) * X_P + kb) * 2);
#pragma unroll
            for (int nt2 = 0; nt2 < 4; ++nt2)
                ldm4(bf_[nt2], bb + (uint32_t)((64 * ngp + 16 * nt2 + lrow) * X_P + kb) * 2);
#pragma unroll
            for (int nt2 = 0; nt2 < 4; ++nt2) {
#pragma unroll
                for (int hf2 = 0; hf2 < 2; ++hf2) {
                    uint32_t b0 = bf_[nt2][hf2], b1 = bf_[nt2][hf2 + 2];
#pragma unroll
                    for (int mt = 0; mt < 2; ++mt)
                        mma16816(acc[mt][2 * nt2 + hf2],
                                 af[mt][0], af[mt][1], af[mt][2], af[mt][3], b0, b1);
                }
            }
        }
        __syncthreads();
    }
#pragma unroll
    for (int mt = 0; mt < 2; ++mt) {
        int mrow = m0 + 32 * mg + 16 * mt + g;
        float bv0 = g_ball[mrow], bv1 = g_ball[mrow + 8];
#pragma unroll
        for (int nt = 0; nt < 8; ++nt) {
            int nrow = n0 + 64 * ngp + 8 * nt + 2 * c4;
            g_XW[(size_t)nrow * NG + mrow]           = acc[mt][nt][0] + bv0;
            g_XW[(size_t)(nrow + 1) * NG + mrow]     = acc[mt][nt][1] + bv0;
            g_XW[(size_t)nrow * NG + mrow + 8]       = acc[mt][nt][2] + bv1;
            g_XW[(size_t)(nrow + 1) * NG + mrow + 8] = acc[mt][nt][3] + bv1;
        }
    }
}

// ================= persistent recurrence: 3-stage single-sync pipeline =================
// 128 CTAs x 512 threads. CTA: M32 x N64. Wh-hi resident; h-hi/h-lo/Wh-lo streamed
// per k=128 chunk through 3 stages (one __syncthreads per chunk, issue depth 2).
// Warp grid: mg(2) x ngp(4) x kg(2) k-split into two D partials.
#define R_PWH 1032                     // Wh-hi pitch (el): 2064B % 128 == 16 -> ldmatrix-safe
#define R_WHB (32 * R_PWH * 2)         // 66048 resident Wh-hi
#define R_P   136                      // streamed pitch (el): 272B % 128 == 16
#define H_SZ  (64 * R_P * 2)           // 17408 per h split
#define WL_OFF (2 * H_SZ)              // 34816: Wh-lo chunk offset within stage
#define WL_SZ (32 * R_P * 2)           // 8704
#define SBUF  (WL_OFF + WL_SZ)         // 43520 per stage
#define R_DOF (R_WHB + 3 * SBUF)       // 196608
#define R_DSZ (32 * 65 * 4)            // 8320 per D partial
#define R_SMEM (R_DOF + 2 * R_DSZ)     // 213248

__device__ __forceinline__ void recur_issueB(uint32_t sb, int tid, int ck, int par, int m0) {
    uint32_t st = sb + R_WHB + (uint32_t)(ck % 3) * SBUF;
#pragma unroll
    for (int it = 0; it < 2; ++it) {
        int j = tid + it * 512;            // 1024 16B-units per h split
        int n = j >> 4, kq = j & 15;
        uint32_t d = st + (uint32_t)(n * R_P + kq * 8) * 2;
        const bf16* s = g_h2[par] + (size_t)n * KK2 + ck * 128 + kq * 8;
        cp16(d,        s);                 // h hi chunk
        cp16(d + H_SZ, s + 1024);          // h lo chunk
    }
    {   // Wh-lo chunk: 512 16B-units
        int r = tid >> 4, kq = tid & 15;
        uint32_t d = st + WL_OFF + (uint32_t)(r * R_P + kq * 8) * 2;
        cp16(d, g_Wh2 + (size_t)(m0 + r) * KK2 + 1024 + ck * 128 + kq * 8);
    }
    CP_COMMIT();
}

__device__ __forceinline__ float sigf(float x) { return 1.0f / (1.0f + __expf(-x)); }

// Two-level grid barrier: 16 groups of 8 CTAs (padded counters), root of 16.
__device__ __forceinline__ void grid_barrier(int t) {
    __threadfence();                     // order this thread's h writes
    __syncthreads();
    if (threadIdx.x == 0) {
        int grp = blockIdx.x >> 3;
        unsigned r = atomicAdd(&g_barg[t * 512 + grp * 32], 1u);
        if (r == 7u) atomicAdd(&g_bar[t], 1u);
        while (*((volatile unsigned int*)&g_bar[t]) < 16u) { __nanosleep(32); }
        __threadfence();
    }
    __syncthreads();
}

__global__ __launch_bounds__(512) void recur_kernel(float* __restrict__ out) {
    extern __shared__ __align__(16) char smem[];
    uint32_t sb = smem_u32(smem);
    const int tid = threadIdx.x;
    const int w = tid >> 5, lane = tid & 31;
    const int g = lane >> 2, c4 = lane & 3;
    const int m0 = blockIdx.x * 32;     // gate-row base
    const int j0 = blockIdx.x * 8;      // hidden-unit base
    const int mg = w & 1;               // m16 tile
    const int ngp = (w >> 1) & 3;       // n16 tile
    const int kg = w >> 3;              // k-split half
    const int lrow = lane & 15;
    const int lko  = (lane >> 4) * 8;

    // ---- load this CTA's Wh-hi slice into SMEM once ----
#pragma unroll
    for (int it = 0; it < 8; ++it) {
        int j = tid + it * 512;             // 4096 16B-units (32 rows x 128 units)
        int r = j >> 7, kq = j & 127;
        uint32_t off = (uint32_t)(r * R_PWH + kq * 8) * 2;
        uint4 v = *(const uint4*)(g_Wh2 + (size_t)(m0 + r) * KK2 + kq * 8);
        sts128(sb + off, v);
    }
    __syncthreads();

    // ---- t = 0 (h_{-1} = 0): 1 cell per thread ----
    float cc;
    const int cu = tid >> 6, cb = tid & 63;
    {
        float4 xw = *(const float4*)(g_XW + (size_t)cb * NG + m0 + 4 * cu);
        float i = sigf(xw.y), gg = tanhf(xw.z), o = sigf(xw.w);
        cc = i * gg;
        float h = o * tanhf(cc);
        out[(size_t)cb * HH + j0 + cu] = h;
        bf16 hh = __float2bfloat16(h);
        g_h2[0][cb * KK2 + j0 + cu]        = hh;
        g_h2[0][cb * KK2 + 1024 + j0 + cu] = __float2bfloat16(h - __bfloat162float(hh));
    }
    grid_barrier(0);

    const uint32_t d0 = sb + R_DOF;
    const uint32_t dk = d0 + (uint32_t)kg * R_DSZ;
    const int kk0 = kg * 4;
    for (int t = 1; t < TT; ++t) {
        const int rpar = (t - 1) & 1;
        const int wpar = t & 1;
        float acc[2][4] = {{0.f, 0.f, 0.f, 0.f}, {0.f, 0.f, 0.f, 0.f}};
        recur_issueB(sb, tid, 0, rpar, m0);
        recur_issueB(sb, tid, 1, rpar, m0);
        // prefetch this step's xw off the post-GEMM critical path
        float4 xw = *(const float4*)(g_XW + (size_t)t * BG + (size_t)cb * NG + m0 + 4 * cu);
        for (int ck = 0; ck < 8; ++ck) {
            if (ck < 7) CP_WAIT1(); else CP_WAIT0();
            __syncthreads();                       // one sync per chunk (3-stage safety)
            if (ck < 6) recur_issueB(sb, tid, ck + 2, rpar, m0);
            uint32_t st = sb + R_WHB + (uint32_t)(ck % 3) * SBUF;
            const int kc = ck * 128;
#pragma unroll
            for (int kk = 0; kk < 4; ++kk) {
                const int kkl = kk0 + kk;          // local k-tile 0..7
                uint32_t ahoff = sb + (uint32_t)((16 * mg + lrow) * R_PWH + kc + kkl * 16 + lko) * 2;
                uint32_t aloff = st + WL_OFF + (uint32_t)((16 * mg + lrow) * R_P + kkl * 16 + lko) * 2;
                uint32_t bhoff = st + (uint32_t)((16 * ngp + lrow) * R_P + kkl * 16 + lko) * 2;
                uint32_t ah[4], al[4], bh[4], bl[4];
                ldm4(ah, ahoff);                   // Wh-hi (resident)
                ldm4(al, aloff);                   // Wh-lo (streamed)
                ldm4(bh, bhoff);                   // h hi
                ldm4(bl, bhoff + H_SZ);            // h lo
                mma16816(acc[0], ah[0], ah[1], ah[2], ah[3], bh[0], bh[2]);
                mma16816(acc[1], ah[0], ah[1], ah[2], ah[3], bh[1], bh[3]);
                mma16816(acc[0], al[0], al[1], al[2], al[3], bh[0], bh[2]);
                mma16816(acc[1], al[0], al[1], al[2], al[3], bh[1], bh[3]);
                mma16816(acc[0], ah[0], ah[1], ah[2], ah[3], bl[0], bl[2]);
                mma16816(acc[1], ah[0], ah[1], ah[2], ah[3], bl[1], bl[3]);
            }
        }
        // ---- stage D partial into this kg's smem buffer ----
#pragma unroll
        for (int s = 0; s < 2; ++s) {
            int r = 16 * mg + g;
            int nb = 16 * ngp + 8 * s + 2 * c4;
            sts_f32(dk + (uint32_t)(r * 65 + nb) * 4,           acc[s][0]);
            sts_f32(dk + (uint32_t)(r * 65 + nb + 1) * 4,       acc[s][1]);
            sts_f32(dk + (uint32_t)((r + 8) * 65 + nb) * 4,     acc[s][2]);
            sts_f32(dk + (uint32_t)((r + 8) * 65 + nb + 1) * 4, acc[s][3]);
        }
        __syncthreads();
        // ---- cell update: 1 cell per thread, sum the two k-split partials ----
        {
            float hf  = lds_f32(d0 + (uint32_t)((4 * cu + 0) * 65 + cb) * 4)
                      + lds_f32(d0 + R_DSZ + (uint32_t)((4 * cu + 0) * 65 + cb) * 4);
            float hi_ = lds_f32(d0 + (uint32_t)((4 * cu + 1) * 65 + cb) * 4)
                      + lds_f32(d0 + R_DSZ + (uint32_t)((4 * cu + 1) * 65 + cb) * 4);
            float hg  = lds_f32(d0 + (uint32_t)((4 * cu + 2) * 65 + cb) * 4)
                      + lds_f32(d0 + R_DSZ + (uint32_t)((4 * cu + 2) * 65 + cb) * 4);
            float ho  = lds_f32(d0 + (uint32_t)((4 * cu + 3) * 65 + cb) * 4)
                      + lds_f32(d0 + R_DSZ + (uint32_t)((4 * cu + 3) * 65 + cb) * 4);
            float f  = sigf(xw.x + hf);
            float i  = sigf(xw.y + hi_);
            float gg = tanhf(xw.z + hg);
            float o  = sigf(xw.w + ho);
            cc = f * cc + i * gg;
            float h = o * tanhf(cc);
            out[(size_t)t * BH + (size_t)cb * HH + j0 + cu] = h;
            bf16 hh = __float2bfloat16(h);
            g_h2[wpar][cb * KK2 + j0 + cu]        = hh;
            g_h2[wpar][cb * KK2 + 1024 + j0 + cu] = __float2bfloat16(h - __bfloat162float(hh));
            if (t == TT - 1) {
                out[(size_t)TT * BH + (size_t)cb * HH + j0 + cu] = h;          // hx
                out[(size_t)TT * BH + BH + (size_t)cb * HH + j0 + cu] = cc;    // cx
            }
        }
        if (t < TT - 1) grid_barrier(t);
    }
}

// ---------------- launch ----------------
extern "C" void kernel_launch(void* const* d_in, const int* in_sizes, int n_in,
                              void* d_out, int out_size) {
    const float* inputs = (const float*)d_in[0];
    const float* Wf = (const float*)d_in[1];
    const float* bf_ = (const float*)d_in[2];
    const float* Wi = (const float*)d_in[3];
    const float* bi_ = (const float*)d_in[4];
    const float* Wg = (const float*)d_in[5];
    const float* bg_ = (const float*)d_in[6];
    const float* Wo = (const float*)d_in[7];
    const float* bo_ = (const float*)d_in[8];
    float* out = (float*)d_out;
    (void)in_sizes; (void)n_in; (void)out_size;

    cudaFuncSetAttribute(xproj_kernel, cudaFuncAttributeMaxDynamicSharedMemorySize, X_SMEM);
    cudaFuncSetAttribute(recur_kernel, cudaFuncAttributeMaxDynamicSharedMemorySize, R_SMEM);

    // 1) repack (K-MAJOR convention — correct bias) + zero both barrier levels
    repack_kernel<<<(KK * NG) / 256, 256>>>(Wf, Wi, Wg, Wo, bf_, bi_, bg_, bo_);

    // 2) split inputs into [hi|lo]
    convx_kernel<<<(TT * BB * KK) / 256, 256>>>(inputs);

    // 3) x-projections (at mma.sync tensor roofline)
    xproj_kernel<<<dim3(32, 256), 256, X_SMEM>>>();

    // 4) persistent recurrence: 3-stage pipeline, two-level barrier
    recur_kernel<<<128, 512, R_SMEM>>>(out);
}